// round 7
// baseline (speedup 1.0000x reference)
#include <cuda_runtime.h>
#include <math.h>

// PennyLaneBasicDQN: 16-qubit VQC (RY embed + 4x[Rot,CZ chain]) + linear head.
// Heisenberg light-cone + Pauli-transfer-matrix method (verified R3..R6).
// R7: R5 stage structure, but (a) warp-local scheduling for strides<=16 ->
// 9 CTA barriers instead of 18 (third buffer for CZ output), (b) 16 threads
// per sample in the contraction, chunks of 16 samples -> grid 512 CTAs.

#define NQ 16
#define NA 6
#define BATCHSZ 512
#define NCHUNK 32
#define SPC 16            // samples per chunk
#define QS 68             // padded q-stride (floats) in final tensor
#define AS 280            // padded slice(p0)-stride = 4*QS + 8

__device__ float g_z[BATCHSZ * NQ];
__device__ int   g_cnt[NCHUNK] = {0};

struct C2 { float x, y; };
__device__ __forceinline__ C2 cmk(float a, float b){ C2 r; r.x=a; r.y=b; return r; }
__device__ __forceinline__ C2 cml(C2 a, C2 b){ return cmk(a.x*b.x - a.y*b.y, a.x*b.y + a.y*b.x); }
__device__ __forceinline__ C2 cad(C2 a, C2 b){ return cmk(a.x+b.x, a.y+b.y); }

// Column p of the 4x4 real PTM of conjugation O -> U^dag O U
__device__ __forceinline__ void ptm_col(const C2 u[4], int p, float col[4]) {
    C2 ud00 = cmk(u[0].x, -u[0].y), ud01 = cmk(u[2].x, -u[2].y);
    C2 ud10 = cmk(u[1].x, -u[1].y), ud11 = cmk(u[3].x, -u[3].y);
    C2 s00, s01, s10, s11;                 // sigma_p * U
    if (p == 0)      { s00=u[0]; s01=u[1]; s10=u[2]; s11=u[3]; }
    else if (p == 1) { s00=u[2]; s01=u[3]; s10=u[0]; s11=u[1]; }
    else if (p == 2) {
        s00 = cmk( u[2].y, -u[2].x);
        s01 = cmk( u[3].y, -u[3].x);
        s10 = cmk(-u[0].y,  u[0].x);
        s11 = cmk(-u[1].y,  u[1].x);
    } else           { s00=u[0]; s01=u[1]; s10=cmk(-u[2].x,-u[2].y); s11=cmk(-u[3].x,-u[3].y); }
    C2 A00 = cad(cml(ud00, s00), cml(ud01, s10));
    C2 A01 = cad(cml(ud00, s01), cml(ud01, s11));
    C2 A10 = cad(cml(ud10, s00), cml(ud11, s10));
    C2 A11 = cad(cml(ud10, s01), cml(ud11, s11));
    col[0] = 0.5f*(A00.x + A11.x);
    col[1] = 0.5f*(A01.x + A10.x);
    col[2] = 0.5f*(A10.y - A01.y);
    col[3] = 0.5f*(A00.x - A11.x);
}

// PennyLane Rot(phi,theta,omega) = RZ(omega) RY(theta) RZ(phi)
__device__ __forceinline__ void rot_u(const float* wp, C2 u[4]) {
    float phi = wp[0], th = wp[1], om = wp[2];
    float c, s; __sincosf(0.5f*th, &s, &c);
    float epx, epy, emx, emy;
    __sincosf(-0.5f*(phi+om), &epy, &epx);
    __sincosf(-0.5f*(phi-om), &emy, &emx);
    u[0] = cmk( epx*c,  epy*c);
    u[1] = cmk(-emx*s,  emy*s);
    u[2] = cmk( emx*s,  emy*s);
    u[3] = cmk( epx*c, -epy*c);
}

// One 4x4 PTM applied along axis with stride s; 1 fiber per thread.
__device__ __forceinline__ void stage(const float* __restrict__ src,
                                      float* __restrict__ dst,
                                      const float* __restrict__ M,
                                      int s, int tid) {
    int base = (tid / s) * (4 * s) + (tid % s);
    float c0 = src[base], c1 = src[base+s], c2 = src[base+2*s], c3 = src[base+3*s];
    dst[base]     = M[0] *c0 + M[1] *c1 + M[2] *c2 + M[3] *c3;
    dst[base+s]   = M[4] *c0 + M[5] *c1 + M[6] *c2 + M[7] *c3;
    dst[base+2*s] = M[8] *c0 + M[9] *c1 + M[10]*c2 + M[11]*c3;
    dst[base+3*s] = M[12]*c0 + M[13]*c1 + M[14]*c2 + M[15]*c3;
}

// CZ chain permutation-with-sign; reads own warp slice, scatters globally.
__device__ __forceinline__ void czstage(const float* __restrict__ src,
                                        float* __restrict__ dst,
                                        int i, int tid, bool pad) {
    float4 inv = reinterpret_cast<const float4*>(src)[tid];
    float vals[4] = {inv.x, inv.y, inv.z, inv.w};
    #pragma unroll
    for (int j = 0; j < 4; j++) {
        int e = (tid << 2) | j;
        int p[5] = {(e>>8)&3, (e>>6)&3, (e>>4)&3, (e>>2)&3, e&3};
        float sg = vals[j];
        #pragma unroll
        for (int a = 0; a < 4; a++) {
            int wl = i - 2 + a;
            if (wl >= 0 && wl + 1 < NQ) {
                int pa = p[a], pb = p[a+1];
                bool xl = (pa==1)||(pa==2), xr = (pb==1)||(pb==2);
                if (xl && xr && pa != pb) sg = -sg;
                if (xr) p[a]   = pa ^ 3;
                if (xl) p[a+1] = pb ^ 3;
            }
        }
        int off = pad ? (p[0]*AS + p[1]*QS + p[2]*16 + p[3]*4 + p[4])
                      : ((p[0]<<8)|(p[1]<<6)|(p[2]<<4)|(p[3]<<2)|p[4]);
        dst[off] = sg;
    }
}

__global__ __launch_bounds__(256)
void vqc_fused(const float* __restrict__ x, const float* __restrict__ W,
               const float* __restrict__ fcw, const float* __restrict__ fcb,
               float* __restrict__ out)
{
    __shared__ __align__(16) float tA[1024];
    __shared__ __align__(16) float tB[1024];
    __shared__ __align__(16) float tC[4 * AS];   // CZ output / final padded tensor
    __shared__ float PT[15][16];
    __shared__ float bx[7][3], bz[7][3];
    __shared__ int s_elect;

    const int i     = blockIdx.x;
    const int chunk = blockIdx.y;
    const int tid   = threadIdx.x;
    const int sl    = tid >> 4;           // local sample 0..15
    const int sub   = tid & 15;           // 16 threads per sample
    const int as    = sub & 3;            // p0 slice
    const int q     = sub >> 2;           // p1 value
    const int b     = chunk * SPC + sl;

    // issue x loads early
    float xv[7];
    #pragma unroll
    for (int k = 0; k < 7; k++) {
        int w = i - 3 + k;
        xv[k] = (w >= 0 && w < NQ) ? x[b*NQ + w] : 0.f;
    }

    // ---- prologue: column-parallel PTM + Bloch construction ----
    if (tid < 60) {
        int id = tid >> 2, p = tid & 3;
        int l = 1 + id / 5, a = id % 5;
        int w = i - 2 + a;
        float col[4];
        if (w >= 0 && w < NQ) {
            C2 u[4]; rot_u(W + (l*NQ + w)*3, u);
            ptm_col(u, p, col);
        } else {
            #pragma unroll
            for (int qq = 0; qq < 4; qq++) col[qq] = (qq == p) ? 1.f : 0.f;
        }
        #pragma unroll
        for (int qq = 0; qq < 4; qq++) PT[id][qq*4 + p] = col[qq];
    } else if (tid >= 64 && tid < 78) {
        int id = tid - 64;
        int k = id >> 1;
        int p = (id & 1) ? 3 : 1;
        int w = i - 3 + k;
        float col[4] = {0.f, 0.f, 0.f, 0.f};
        if (w >= 0 && w < NQ) {
            C2 u[4]; rot_u(W + w*3, u);
            C2 v[4] = { cmk(u[0].x,-u[0].y), cmk(u[2].x,-u[2].y),
                        cmk(u[1].x,-u[1].y), cmk(u[3].x,-u[3].y) };
            ptm_col(v, p, col);
        }
        float* dstv = (p == 1) ? bx[k] : bz[k];
        dstv[0] = col[1]; dstv[1] = col[2]; dstv[2] = col[3];
    }
    for (int j = tid; j < 1024; j += 256) tA[j] = (j == 48) ? 1.f : 0.f; // Z at p2
    __syncthreads();

    // per-sample Bloch vectors
    float m[7][3];
    #pragma unroll
    for (int k = 0; k < 7; k++) {
        float sx, cx; __sincosf(xv[k], &sx, &cx);
        m[k][0] = sx*bx[k][0] + cx*bz[k][0];
        m[k][1] = sx*bx[k][1] + cx*bz[k][1];
        m[k][2] = sx*bx[k][2] + cx*bz[k][2];
    }

    // ---- backward conjugation: per layer
    //   s256 [BAR] s64 [BAR] s16 (ws) s4 (ws) s1 (ws) CZ->tC [BAR]
    // strides<=16 are warp-local (warp w owns floats [128w,128w+128)).
    float* in = tA;
    for (int l = 3; l >= 1; l--) {
        const float* M0 = PT[(l-1)*5 + 0];
        const float* M1 = PT[(l-1)*5 + 1];
        const float* M2 = PT[(l-1)*5 + 2];
        const float* M3 = PT[(l-1)*5 + 3];
        const float* M4 = PT[(l-1)*5 + 4];
        float* B0 = (in == tA) ? tB : tA;
        float* B1 = (in == tA) ? tA : tB;

        stage(in, B0, M0, 256, tid);  __syncthreads();
        stage(B0, B1, M1, 64,  tid);  __syncthreads();
        stage(B1, B0, M2, 16,  tid);  __syncwarp();
        stage(B0, B1, M3, 4,   tid);  __syncwarp();
        stage(B1, B0, M4, 1,   tid);  __syncwarp();
        czstage(B0, tC, i, tid, l == 1);
        __syncthreads();
        in = tC;
    }

    // ---- per-sample contraction: 16 threads/sample, thread = (p0=as, p1=q) ----
    float dL = (i - 3 >= 0) ? m[0][2] : 1.f;
    float dR = (i + 3 < NQ) ? m[6][2] : 1.f;
    float v0[4], v1[4], v2[4], v3[4], v4[4];
    v0[0]=1.f; v0[1]=dL*m[1][0]; v0[2]=dL*m[1][1]; v0[3]=m[1][2];
    v1[0]=1.f; v1[1]=m[2][0];    v1[2]=m[2][1];    v1[3]=m[2][2];
    v2[0]=1.f; v2[1]=m[3][0];    v2[2]=m[3][1];    v2[3]=m[3][2];
    v3[0]=1.f; v3[1]=m[4][0];    v3[2]=m[4][1];    v3[3]=m[4][2];
    v4[0]=1.f; v4[1]=dR*m[5][0]; v4[2]=dR*m[5][1]; v4[3]=m[5][2];

    const float* Ta = tC + as * AS + q * QS;
    float acc = 0.f;
    #pragma unroll
    for (int c = 0; c < 4; c++) {
        float sc = 0.f;
        #pragma unroll
        for (int d = 0; d < 4; d++) {
            float4 t4 = *reinterpret_cast<const float4*>(Ta + c*16 + d*4);
            sc += v3[d] * (t4.x*v4[0] + t4.y*v4[1] + t4.z*v4[2] + t4.w*v4[3]);
        }
        acc += v2[c] * sc;
    }
    float z = v0[as] * v1[q] * acc;
    #pragma unroll
    for (int msk = 1; msk < 16; msk <<= 1)
        z += __shfl_xor_sync(0xffffffffu, z, msk);
    if (sub == 0) g_z[b * NQ + i] = z;

    // ---- fused FC head: last CTA of this chunk does the 16x6 GEMV ----
    __syncthreads();
    if (tid == 0) {
        __threadfence();
        int old = atomicAdd(&g_cnt[chunk], 1);
        int e = (old == NQ - 1);
        if (e) {
            __threadfence();
            atomicExch(&g_cnt[chunk], 0);   // reset for next graph replay
        }
        s_elect = e;
    }
    __syncthreads();
    if (s_elect) {
        tA[tid] = __ldcg(&g_z[chunk * SPC * NQ + tid]);   // 256 = SPC*NQ
        __syncthreads();
        if (tid < SPC * NA) {
            int s = tid / NA, a = tid % NA;
            float acc2 = fcb[a];
            #pragma unroll
            for (int k = 0; k < NQ; k++) acc2 += tA[s*NQ + k] * fcw[a*NQ + k];
            out[(chunk * SPC + s) * NA + a] = acc2;
        }
    }
}

extern "C" void kernel_launch(void* const* d_in, const int* in_sizes, int n_in,
                              void* d_out, int out_size) {
    const float* x   = (const float*)d_in[0];   // [512,16]
    const float* W   = (const float*)d_in[1];   // [4,16,3]
    const float* fcw = (const float*)d_in[2];   // [6,16]
    const float* fcb = (const float*)d_in[3];   // [6]
    float* out = (float*)d_out;                 // [512,6]
    (void)in_sizes; (void)n_in; (void)out_size;
    dim3 grid(NQ, NCHUNK);
    vqc_fused<<<grid, 256>>>(x, W, fcw, fcb, out);
}

// round 8
// speedup vs baseline: 2.4913x; 2.4913x over previous
#include <cuda_runtime.h>
#include <math.h>

// PennyLaneBasicDQN: 16-qubit VQC (RY embed + 4x[Rot,CZ chain]) + linear head.
// Heisenberg light-cone + Pauli-transfer-matrix method (verified R3..R7).
// R8: exact sparsity of the backward evolution:
//   layer3 -> 4 nonzeros (init), D2+layer2 -> 64-el tensor (in REGISTERS,
//   per-warp redundant, shfl butterflies), D1 -> compact 256 (edges in {I,Z}),
//   layer1 axes 1-3 on 256, then ONE fused stage: edge-axis expansion
//   (2->4 via PTM cols I,Z) + D0 CZ perm scatter into padded 1024 tensor.
// Grid (16 qubits x 8 chunks of 64 samples), fused FC head.

#define NQ 16
#define NA 6
#define BATCHSZ 512
#define NCHUNK 8
#define SPC 64
#define APAD 264          // padded p0-slice stride (floats)

__device__ float g_z[BATCHSZ * NQ];
__device__ int   g_cnt[NCHUNK] = {0};

struct C2 { float x, y; };
__device__ __forceinline__ C2 cmk(float a, float b){ C2 r; r.x=a; r.y=b; return r; }
__device__ __forceinline__ C2 cml(C2 a, C2 b){ return cmk(a.x*b.x - a.y*b.y, a.x*b.y + a.y*b.x); }
__device__ __forceinline__ C2 cad(C2 a, C2 b){ return cmk(a.x+b.x, a.y+b.y); }

// Column p of the 4x4 real PTM of conjugation O -> U^dag O U
__device__ __forceinline__ void ptm_col(const C2 u[4], int p, float col[4]) {
    C2 ud00 = cmk(u[0].x, -u[0].y), ud01 = cmk(u[2].x, -u[2].y);
    C2 ud10 = cmk(u[1].x, -u[1].y), ud11 = cmk(u[3].x, -u[3].y);
    C2 s00, s01, s10, s11;                 // sigma_p * U
    if (p == 0)      { s00=u[0]; s01=u[1]; s10=u[2]; s11=u[3]; }
    else if (p == 1) { s00=u[2]; s01=u[3]; s10=u[0]; s11=u[1]; }
    else if (p == 2) {
        s00 = cmk( u[2].y, -u[2].x);
        s01 = cmk( u[3].y, -u[3].x);
        s10 = cmk(-u[0].y,  u[0].x);
        s11 = cmk(-u[1].y,  u[1].x);
    } else           { s00=u[0]; s01=u[1]; s10=cmk(-u[2].x,-u[2].y); s11=cmk(-u[3].x,-u[3].y); }
    C2 A00 = cad(cml(ud00, s00), cml(ud01, s10));
    C2 A01 = cad(cml(ud00, s01), cml(ud01, s11));
    C2 A10 = cad(cml(ud10, s00), cml(ud11, s10));
    C2 A11 = cad(cml(ud10, s01), cml(ud11, s11));
    col[0] = 0.5f*(A00.x + A11.x);
    col[1] = 0.5f*(A01.x + A10.x);
    col[2] = 0.5f*(A10.y - A01.y);
    col[3] = 0.5f*(A00.x - A11.x);
}

// PennyLane Rot(phi,theta,omega) = RZ(omega) RY(theta) RZ(phi)
__device__ __forceinline__ void rot_u(const float* wp, C2 u[4]) {
    float phi = wp[0], th = wp[1], om = wp[2];
    float c, s; __sincosf(0.5f*th, &s, &c);
    float epx, epy, emx, emy;
    __sincosf(-0.5f*(phi+om), &epy, &epx);
    __sincosf(-0.5f*(phi-om), &emy, &emx);
    u[0] = cmk( epx*c,  epy*c);
    u[1] = cmk(-emx*s,  emy*s);
    u[2] = cmk( emx*s,  emy*s);
    u[3] = cmk( epx*c, -epy*c);
}

__global__ __launch_bounds__(256)
void vqc_fused(const float* __restrict__ x, const float* __restrict__ W,
               const float* __restrict__ fcw, const float* __restrict__ fcb,
               float* __restrict__ out)
{
    __shared__ float PT[15][16];          // conj-PTMs: layers 1..3 x window pos 0..4
    __shared__ float bx[7][3], bz[7][3];  // layer-0 Bloch columns, wires i-3..i+3
    __shared__ __align__(8)  float t256a[256];
    __shared__ __align__(8)  float t256b[256];
    __shared__ __align__(16) float tF[4 * APAD];
    __shared__ int s_elect;

    const int i     = blockIdx.x;         // measured qubit
    const int chunk = blockIdx.y;         // 64-sample chunk
    const int tid   = threadIdx.x;
    const int lane  = tid & 31;
    const int sl    = tid >> 2;           // local sample 0..63
    const int as    = tid & 3;            // p0 slice in contraction
    const int b     = chunk * SPC + sl;

    // issue x loads early (hidden behind prologue)
    float xv[7];
    #pragma unroll
    for (int k = 0; k < 7; k++) {
        int w = i - 3 + k;
        xv[k] = (w >= 0 && w < NQ) ? x[b*NQ + w] : 0.f;
    }

    // ---- prologue: column-parallel PTM + Bloch construction ----
    if (tid < 60) {
        int id = tid >> 2, p = tid & 3;
        int l = 1 + id / 5, a = id % 5;
        int w = i - 2 + a;
        float col[4];
        if (w >= 0 && w < NQ) {
            C2 u[4]; rot_u(W + (l*NQ + w)*3, u);
            ptm_col(u, p, col);
        } else {
            #pragma unroll
            for (int q = 0; q < 4; q++) col[q] = (q == p) ? 1.f : 0.f;
        }
        #pragma unroll
        for (int q = 0; q < 4; q++) PT[id][q*4 + p] = col[q];
    } else if (tid >= 64 && tid < 78) {
        int id = tid - 64;
        int k = id >> 1;
        int p = (id & 1) ? 3 : 1;
        int w = i - 3 + k;
        float col[4] = {0.f, 0.f, 0.f, 0.f};
        if (w >= 0 && w < NQ) {
            C2 u[4]; rot_u(W + w*3, u);
            C2 v[4] = { cmk(u[0].x,-u[0].y), cmk(u[2].x,-u[2].y),
                        cmk(u[1].x,-u[1].y), cmk(u[3].x,-u[3].y) };
            ptm_col(v, p, col);
        }
        float* dstv = (p == 1) ? bx[k] : bz[k];
        dstv[0] = col[1]; dstv[1] = col[2]; dstv[2] = col[3];
    }
    t256a[tid] = 0.f;                     // zero-fill compact D1 target
    __syncthreads();

    // per-sample Bloch vectors
    float m[7][3];
    #pragma unroll
    for (int k = 0; k < 7; k++) {
        float sx, cx; __sincosf(xv[k], &sx, &cx);
        m[k][0] = sx*bx[k][0] + cx*bz[k][0];
        m[k][1] = sx*bx[k][1] + cx*bz[k][1];
        m[k][2] = sx*bx[k][2] + cx*bz[k][2];
    }

    // ---- small 64-tensor (positions 1,2,3) in registers, per-warp ----
    // init = Z conjugated by R3(center) then D2 (pairs (1,2),(2,3) if wires exist)
    const int ex1 = (i >= 1), ex2 = (i <= 14);
    const int fX = (ex1 ? 48 : 0) + 4 + (ex2 ? 3 : 0);
    const int fY = fX + 4;
    const float cI = PT[12][3], cX = PT[12][7], cY = PT[12][11], cZ = PT[12][15];
    float v0, v1;   // lane holds f=lane (v0) and f=32+lane (v1); f = p1*16+p2*4+p3
    {
        int f0 = lane, f1 = 32 + lane;
        v0 = (f0==0)?cI : (f0==12)?cZ : (f0==fX)?cX : (f0==fY)?cY : 0.f;
        v1 = (f1==0)?cI : (f1==12)?cZ : (f1==fX)?cX : (f1==fY)?cY : 0.f;
    }
    // layer-2 axis p1 (PT[6]): p1 split across (reg, lane>=16)
    {
        const float* M = PT[6];
        float o0 = __shfl_xor_sync(0xffffffffu, v0, 16);
        float o1 = __shfl_xor_sync(0xffffffffu, v1, 16);
        int q0 = (lane >> 4) & 1;          // own v0's p1; v1's p1 = q0^2
        int r0 = q0, r1 = q0 ^ 2;
        float n0 = M[r0*4+q0]*v0 + M[r0*4+(q0^1)]*o0 + M[r0*4+(q0^2)]*v1 + M[r0*4+(q0^3)]*o1;
        float n1 = M[r1*4+q0]*v0 + M[r1*4+(q0^1)]*o0 + M[r1*4+(q0^2)]*v1 + M[r1*4+(q0^3)]*o1;
        v0 = n0; v1 = n1;
    }
    // layer-2 axis p2 (PT[7]): xor 4,8,12 within lane
    {
        const float* M = PT[7];
        int po = (lane >> 2) & 3;
        float a1 = __shfl_xor_sync(0xffffffffu, v0, 4);
        float a2 = __shfl_xor_sync(0xffffffffu, v0, 8);
        float a3 = __shfl_xor_sync(0xffffffffu, v0, 12);
        float b1 = __shfl_xor_sync(0xffffffffu, v1, 4);
        float b2 = __shfl_xor_sync(0xffffffffu, v1, 8);
        float b3 = __shfl_xor_sync(0xffffffffu, v1, 12);
        v0 = M[po*4+po]*v0 + M[po*4+(po^1)]*a1 + M[po*4+(po^2)]*a2 + M[po*4+(po^3)]*a3;
        v1 = M[po*4+po]*v1 + M[po*4+(po^1)]*b1 + M[po*4+(po^2)]*b2 + M[po*4+(po^3)]*b3;
    }
    // layer-2 axis p3 (PT[8]): xor 1,2,3
    {
        const float* M = PT[8];
        int po = lane & 3;
        float a1 = __shfl_xor_sync(0xffffffffu, v0, 1);
        float a2 = __shfl_xor_sync(0xffffffffu, v0, 2);
        float a3 = __shfl_xor_sync(0xffffffffu, v0, 3);
        float b1 = __shfl_xor_sync(0xffffffffu, v1, 1);
        float b2 = __shfl_xor_sync(0xffffffffu, v1, 2);
        float b3 = __shfl_xor_sync(0xffffffffu, v1, 3);
        v0 = M[po*4+po]*v0 + M[po*4+(po^1)]*a1 + M[po*4+(po^2)]*a2 + M[po*4+(po^3)]*a3;
        v1 = M[po*4+po]*v1 + M[po*4+(po^1)]*b1 + M[po*4+(po^2)]*b2 + M[po*4+(po^3)]*b3;
    }
    // ---- D1 (pairs a=0..3, czstage semantics) -> compact 256: [b0][p1p2p3][b4]
    {
        const int exA0 = (i >= 2), exA1 = (i >= 1), exA2 = (i <= 14), exA3 = (i <= 13);
        #pragma unroll
        for (int r = 0; r < 2; r++) {
            int f = r*32 + lane;
            int p1 = f >> 4, p2 = (f >> 2) & 3, p3 = f & 3;
            float sg = r ? v1 : v0;
            int b0 = (exA0 && (p1 == 1 || p1 == 2)) ? 1 : 0;
            if (exA1) {
                bool xl = (p1==1)||(p1==2), xr = (p2==1)||(p2==2);
                if (xl && xr && p1 != p2) sg = -sg;
                if (xr) p1 ^= 3;
                if (xl) p2 ^= 3;
            }
            if (exA2) {
                bool xl = (p2==1)||(p2==2), xr = (p3==1)||(p3==2);
                if (xl && xr && p2 != p3) sg = -sg;
                if (xr) p2 ^= 3;
                if (xl) p3 ^= 3;
            }
            int b4 = (exA3 && (p3 == 1 || p3 == 2)) ? 1 : 0;
            t256a[b0*128 + (p1*16 + p2*4 + p3)*2 + b4] = sg;  // all warps: same values
        }
    }
    __syncthreads();

    // ---- layer-1 axes p1,p2,p3 on compact 256 (strides 32,8,2) ----
    {   // axis p1, PT[1]
        const float* M = PT[1];
        int e = tid, p = (e >> 5) & 3, base = e - (p << 5);
        t256b[e] = M[p*4+0]*t256a[base] + M[p*4+1]*t256a[base+32]
                 + M[p*4+2]*t256a[base+64] + M[p*4+3]*t256a[base+96];
    }
    __syncthreads();
    {   // axis p2, PT[2]
        const float* M = PT[2];
        int e = tid, p = (e >> 3) & 3, base = e - (p << 3);
        t256a[e] = M[p*4+0]*t256b[base] + M[p*4+1]*t256b[base+8]
                 + M[p*4+2]*t256b[base+16] + M[p*4+3]*t256b[base+24];
    }
    __syncthreads();
    {   // axis p3, PT[3]
        const float* M = PT[3];
        int e = tid, p = (e >> 1) & 3, base = e - (p << 1);
        t256b[e] = M[p*4+0]*t256a[base] + M[p*4+1]*t256a[base+2]
                 + M[p*4+2]*t256a[base+4] + M[p*4+3]*t256a[base+6];
    }
    __syncthreads();

    // ---- fused: edge-axis expansion (p0,p4 via PTM cols I,Z) + D0 CZ scatter ----
    {
        int p0 = tid >> 6;
        int fm = tid & 63;
        float2 T0 = *reinterpret_cast<const float2*>(&t256b[fm*2]);        // b0=0
        float2 T1 = *reinterpret_cast<const float2*>(&t256b[128 + fm*2]);  // b0=1
        float c00 = PT[0][p0*4], c0z = PT[0][p0*4+3];
        float g0 = c00*T0.x + c0z*T1.x;   // b4=0
        float gz = c00*T0.y + c0z*T1.y;   // b4=1
        #pragma unroll
        for (int j = 0; j < 4; j++) {     // j = p4
            float sg = PT[4][j*4]*g0 + PT[4][j*4+3]*gz;
            int e = (tid << 2) | j;
            int p[5] = {(e>>8)&3, (e>>6)&3, (e>>4)&3, (e>>2)&3, e&3};
            #pragma unroll
            for (int a = 0; a < 4; a++) {
                int wl = i - 2 + a;
                if (wl >= 0 && wl + 1 < NQ) {
                    int pa = p[a], pb = p[a+1];
                    bool xl = (pa==1)||(pa==2), xr = (pb==1)||(pb==2);
                    if (xl && xr && pa != pb) sg = -sg;
                    if (xr) p[a]   = pa ^ 3;
                    if (xl) p[a+1] = pb ^ 3;
                }
            }
            tF[p[0]*APAD + (p[1]<<6) + (p[2]<<4) + (p[3]<<2) + p[4]] = sg;
        }
    }
    __syncthreads();

    // ---- per-sample contraction: 4 threads/sample (p0 slice = as) ----
    float dL = (i - 3 >= 0) ? m[0][2] : 1.f;
    float dR = (i + 3 < NQ) ? m[6][2] : 1.f;
    float v0c[4], v1c[4], v2c[4], v3c[4], v4c[4];
    v0c[0]=1.f; v0c[1]=dL*m[1][0]; v0c[2]=dL*m[1][1]; v0c[3]=m[1][2];
    v1c[0]=1.f; v1c[1]=m[2][0];    v1c[2]=m[2][1];    v1c[3]=m[2][2];
    v2c[0]=1.f; v2c[1]=m[3][0];    v2c[2]=m[3][1];    v2c[3]=m[3][2];
    v3c[0]=1.f; v3c[1]=m[4][0];    v3c[2]=m[4][1];    v3c[3]=m[4][2];
    v4c[0]=1.f; v4c[1]=dR*m[5][0]; v4c[2]=dR*m[5][1]; v4c[3]=m[5][2];

    const float4* Ta = reinterpret_cast<const float4*>(tF + as * APAD);
    float sb[4];
    #pragma unroll
    for (int q = 0; q < 4; q++) {
        float acc = 0.f;
        #pragma unroll
        for (int c = 0; c < 4; c++) {
            float sc = 0.f;
            #pragma unroll
            for (int d = 0; d < 4; d++) {
                float4 t4 = Ta[q*16 + c*4 + d];
                sc += v3c[d] * (t4.x*v4c[0] + t4.y*v4c[1] + t4.z*v4c[2] + t4.w*v4c[3]);
            }
            acc += v2c[c] * sc;
        }
        sb[q] = acc;
    }
    float z = v0c[as] * (v1c[0]*sb[0] + v1c[1]*sb[1] + v1c[2]*sb[2] + v1c[3]*sb[3]);
    z += __shfl_xor_sync(0xffffffffu, z, 1);
    z += __shfl_xor_sync(0xffffffffu, z, 2);
    if (as == 0) g_z[b * NQ + i] = z;

    // ---- fused FC head: last CTA of this chunk does the 64x6 GEMV ----
    __syncthreads();
    if (tid == 0) {
        __threadfence();
        int old = atomicAdd(&g_cnt[chunk], 1);
        int e = (old == NQ - 1);
        if (e) {
            __threadfence();
            atomicExch(&g_cnt[chunk], 0);   // reset for next graph replay
        }
        s_elect = e;
    }
    __syncthreads();
    if (s_elect) {
        for (int j = tid; j < SPC * NQ; j += 256)
            tF[j] = __ldcg(&g_z[chunk * SPC * NQ + j]);
        __syncthreads();
        for (int item = tid; item < SPC * NA; item += 256) {
            int s = item / NA, a = item % NA;
            float acc = fcb[a];
            #pragma unroll
            for (int k = 0; k < NQ; k++) acc += tF[s*NQ + k] * fcw[a*NQ + k];
            out[(chunk * SPC + s) * NA + a] = acc;
        }
    }
}

extern "C" void kernel_launch(void* const* d_in, const int* in_sizes, int n_in,
                              void* d_out, int out_size) {
    const float* x   = (const float*)d_in[0];   // [512,16]
    const float* W   = (const float*)d_in[1];   // [4,16,3]
    const float* fcw = (const float*)d_in[2];   // [6,16]
    const float* fcb = (const float*)d_in[3];   // [6]
    float* out = (float*)d_out;                 // [512,6]
    (void)in_sizes; (void)n_in; (void)out_size;
    dim3 grid(NQ, NCHUNK);
    vqc_fused<<<grid, 256>>>(x, W, fcw, fcb, out);
}

// round 9
// speedup vs baseline: 2.4985x; 1.0029x over previous
#include <cuda_runtime.h>
#include <math.h>

// PennyLaneBasicDQN: 16-qubit VQC (RY embed + 4x[Rot,CZ chain]) + linear head.
// Heisenberg light-cone + Pauli-transfer-matrix method (verified R3..R8).
// R9: the whole mid-pipeline (D1 -> layer-1 interior axes) lives in REGISTERS,
// redundant per warp (8 slots/lane), using the involution property of the CZ
// label map (gather form). Only two compute barriers: prologue and the final
// expansion+D0 scatter into the padded smem tensor.

#define NQ 16
#define NA 6
#define BATCHSZ 512
#define NCHUNK 8
#define SPC 64
#define APAD 264          // padded p0-slice stride (floats)

__device__ float g_z[BATCHSZ * NQ];
__device__ int   g_cnt[NCHUNK] = {0};

struct C2 { float x, y; };
__device__ __forceinline__ C2 cmk(float a, float b){ C2 r; r.x=a; r.y=b; return r; }
__device__ __forceinline__ C2 cml(C2 a, C2 b){ return cmk(a.x*b.x - a.y*b.y, a.x*b.y + a.y*b.x); }
__device__ __forceinline__ C2 cad(C2 a, C2 b){ return cmk(a.x+b.x, a.y+b.y); }

// Column p of the 4x4 real PTM of conjugation O -> U^dag O U
__device__ __forceinline__ void ptm_col(const C2 u[4], int p, float col[4]) {
    C2 ud00 = cmk(u[0].x, -u[0].y), ud01 = cmk(u[2].x, -u[2].y);
    C2 ud10 = cmk(u[1].x, -u[1].y), ud11 = cmk(u[3].x, -u[3].y);
    C2 s00, s01, s10, s11;                 // sigma_p * U
    if (p == 0)      { s00=u[0]; s01=u[1]; s10=u[2]; s11=u[3]; }
    else if (p == 1) { s00=u[2]; s01=u[3]; s10=u[0]; s11=u[1]; }
    else if (p == 2) {
        s00 = cmk( u[2].y, -u[2].x);
        s01 = cmk( u[3].y, -u[3].x);
        s10 = cmk(-u[0].y,  u[0].x);
        s11 = cmk(-u[1].y,  u[1].x);
    } else           { s00=u[0]; s01=u[1]; s10=cmk(-u[2].x,-u[2].y); s11=cmk(-u[3].x,-u[3].y); }
    C2 A00 = cad(cml(ud00, s00), cml(ud01, s10));
    C2 A01 = cad(cml(ud00, s01), cml(ud01, s11));
    C2 A10 = cad(cml(ud10, s00), cml(ud11, s10));
    C2 A11 = cad(cml(ud10, s01), cml(ud11, s11));
    col[0] = 0.5f*(A00.x + A11.x);
    col[1] = 0.5f*(A01.x + A10.x);
    col[2] = 0.5f*(A10.y - A01.y);
    col[3] = 0.5f*(A00.x - A11.x);
}

// PennyLane Rot(phi,theta,omega) = RZ(omega) RY(theta) RZ(phi)
__device__ __forceinline__ void rot_u(const float* wp, C2 u[4]) {
    float phi = wp[0], th = wp[1], om = wp[2];
    float c, s; __sincosf(0.5f*th, &s, &c);
    float epx, epy, emx, emy;
    __sincosf(-0.5f*(phi+om), &epy, &epx);
    __sincosf(-0.5f*(phi-om), &emy, &emx);
    u[0] = cmk( epx*c,  epy*c);
    u[1] = cmk(-emx*s,  emy*s);
    u[2] = cmk( emx*s,  emy*s);
    u[3] = cmk( epx*c, -epy*c);
}

__global__ __launch_bounds__(256)
void vqc_fused(const float* __restrict__ x, const float* __restrict__ W,
               const float* __restrict__ fcw, const float* __restrict__ fcb,
               float* __restrict__ out)
{
    __shared__ float PT[15][16];          // conj-PTMs: layers 1..3 x window pos 0..4
    __shared__ float bx[7][3], bz[7][3];  // layer-0 Bloch columns, wires i-3..i+3
    __shared__ __align__(16) float tF[4 * APAD];
    __shared__ int s_elect;

    const int i     = blockIdx.x;         // measured qubit
    const int chunk = blockIdx.y;         // 64-sample chunk
    const int tid   = threadIdx.x;
    const int lane  = tid & 31;
    const int wrp   = tid >> 5;
    const int sl    = tid >> 2;           // local sample 0..63
    const int as    = tid & 3;            // p0 slice in contraction
    const int b     = chunk * SPC + sl;

    // issue x loads early (hidden behind prologue)
    float xv[7];
    #pragma unroll
    for (int k = 0; k < 7; k++) {
        int w = i - 3 + k;
        xv[k] = (w >= 0 && w < NQ) ? x[b*NQ + w] : 0.f;
    }

    // ---- prologue: column-parallel PTM + Bloch construction ----
    if (tid < 60) {
        int id = tid >> 2, p = tid & 3;
        int l = 1 + id / 5, a = id % 5;
        int w = i - 2 + a;
        float col[4];
        if (w >= 0 && w < NQ) {
            C2 u[4]; rot_u(W + (l*NQ + w)*3, u);
            ptm_col(u, p, col);
        } else {
            #pragma unroll
            for (int q = 0; q < 4; q++) col[q] = (q == p) ? 1.f : 0.f;
        }
        #pragma unroll
        for (int q = 0; q < 4; q++) PT[id][q*4 + p] = col[q];
    } else if (tid >= 64 && tid < 78) {
        int id = tid - 64;
        int k = id >> 1;
        int p = (id & 1) ? 3 : 1;
        int w = i - 3 + k;
        float col[4] = {0.f, 0.f, 0.f, 0.f};
        if (w >= 0 && w < NQ) {
            C2 u[4]; rot_u(W + w*3, u);
            C2 v[4] = { cmk(u[0].x,-u[0].y), cmk(u[2].x,-u[2].y),
                        cmk(u[1].x,-u[1].y), cmk(u[3].x,-u[3].y) };
            ptm_col(v, p, col);
        }
        float* dstv = (p == 1) ? bx[k] : bz[k];
        dstv[0] = col[1]; dstv[1] = col[2]; dstv[2] = col[3];
    }
    __syncthreads();                      // B1

    // per-sample Bloch vectors
    float m[7][3];
    #pragma unroll
    for (int k = 0; k < 7; k++) {
        float sx, cx; __sincosf(xv[k], &sx, &cx);
        m[k][0] = sx*bx[k][0] + cx*bz[k][0];
        m[k][1] = sx*bx[k][1] + cx*bz[k][1];
        m[k][2] = sx*bx[k][2] + cx*bz[k][2];
    }

    // ---- 64-tensor (positions 1,2,3) in registers, per-warp (verified R8) ----
    const int ex1 = (i >= 1), ex2 = (i <= 14);
    const int fX = (ex1 ? 48 : 0) + 4 + (ex2 ? 3 : 0);
    const int fY = fX + 4;
    const float cI = PT[12][3], cX = PT[12][7], cY = PT[12][11], cZ = PT[12][15];
    float v0, v1;   // lane holds f=lane (v0) and f=32+lane (v1); f = p1*16+p2*4+p3
    {
        int f0 = lane, f1 = 32 + lane;
        v0 = (f0==0)?cI : (f0==12)?cZ : (f0==fX)?cX : (f0==fY)?cY : 0.f;
        v1 = (f1==0)?cI : (f1==12)?cZ : (f1==fX)?cX : (f1==fY)?cY : 0.f;
    }
    {   // layer-2 axis p1 (PT[6])
        const float* M = PT[6];
        float o0 = __shfl_xor_sync(0xffffffffu, v0, 16);
        float o1 = __shfl_xor_sync(0xffffffffu, v1, 16);
        int q0 = (lane >> 4) & 1;
        int r0 = q0, r1 = q0 ^ 2;
        float n0 = M[r0*4+q0]*v0 + M[r0*4+(q0^1)]*o0 + M[r0*4+(q0^2)]*v1 + M[r0*4+(q0^3)]*o1;
        float n1 = M[r1*4+q0]*v0 + M[r1*4+(q0^1)]*o0 + M[r1*4+(q0^2)]*v1 + M[r1*4+(q0^3)]*o1;
        v0 = n0; v1 = n1;
    }
    {   // layer-2 axis p2 (PT[7])
        const float* M = PT[7];
        int po = (lane >> 2) & 3;
        float a1 = __shfl_xor_sync(0xffffffffu, v0, 4);
        float a2 = __shfl_xor_sync(0xffffffffu, v0, 8);
        float a3 = __shfl_xor_sync(0xffffffffu, v0, 12);
        float b1 = __shfl_xor_sync(0xffffffffu, v1, 4);
        float b2 = __shfl_xor_sync(0xffffffffu, v1, 8);
        float b3 = __shfl_xor_sync(0xffffffffu, v1, 12);
        v0 = M[po*4+po]*v0 + M[po*4+(po^1)]*a1 + M[po*4+(po^2)]*a2 + M[po*4+(po^3)]*a3;
        v1 = M[po*4+po]*v1 + M[po*4+(po^1)]*b1 + M[po*4+(po^2)]*b2 + M[po*4+(po^3)]*b3;
    }
    {   // layer-2 axis p3 (PT[8])
        const float* M = PT[8];
        int po = lane & 3;
        float a1 = __shfl_xor_sync(0xffffffffu, v0, 1);
        float a2 = __shfl_xor_sync(0xffffffffu, v0, 2);
        float a3 = __shfl_xor_sync(0xffffffffu, v0, 3);
        float b1 = __shfl_xor_sync(0xffffffffu, v1, 1);
        float b2 = __shfl_xor_sync(0xffffffffu, v1, 2);
        float b3 = __shfl_xor_sync(0xffffffffu, v1, 3);
        v0 = M[po*4+po]*v0 + M[po*4+(po^1)]*a1 + M[po*4+(po^2)]*a2 + M[po*4+(po^3)]*a3;
        v1 = M[po*4+po]*v1 + M[po*4+(po^1)]*b1 + M[po*4+(po^2)]*b2 + M[po*4+(po^3)]*b3;
    }

    // ---- D1 as a register GATHER (CZ label map is an involution) ----
    // Compact-256 slot layout: C[j + 4*b0], j = q1; lane bits: q2=(lane>>3)&3,
    // q3=(lane>>1)&3, b4=lane&1.  Source = psi(g) with same sign as forward.
    const int exA0 = (i >= 2), exA1 = (i >= 1), exA2 = (i <= 14), exA3 = (i <= 13);
    const int q2 = (lane >> 3) & 3, q3 = (lane >> 1) & 3, b4 = lane & 1;
    float Cg[8];
    {
        const bool need4 = (exA3 && ((q3 == 1) || (q3 == 2)));
        const bool ok4 = (b4 == (need4 ? 1 : 0));
        #pragma unroll
        for (int j = 0; j < 4; j++) {
            int p1 = j, p2 = q2, p3 = q3; float s = 1.f;
            if (exA1) {
                bool xl = (p1==1)||(p1==2), xr = (p2==1)||(p2==2);
                if (xl && xr && p1 != p2) s = -s;
                int np1 = xr ? p1^3 : p1, np2 = xl ? p2^3 : p2;
                p1 = np1; p2 = np2;
            }
            if (exA2) {
                bool xl = (p2==1)||(p2==2), xr = (p3==1)||(p3==2);
                if (xl && xr && p2 != p3) s = -s;
                int np2 = xr ? p2^3 : p2, np3 = xl ? p3^3 : p3;
                p2 = np2; p3 = np3;
            }
            int fsrc = p1*16 + p2*4 + p3;
            float a0 = __shfl_sync(0xffffffffu, v0, fsrc & 31);
            float a1 = __shfl_sync(0xffffffffu, v1, fsrc & 31);
            float val = s * ((fsrc & 32) ? a1 : a0);
            bool need0 = (exA0 && ((p1 == 1) || (p1 == 2)));
            Cg[j]     = (ok4 && !need0) ? val : 0.f;
            Cg[j + 4] = (ok4 &&  need0) ? val : 0.f;
        }
    }

    // ---- layer-1 interior axes, all register/shuffle ----
    {   // axis q1 (PT[1]) : register 4x4 within each b0 group
        const float* M = PT[1];
        float N[8];
        #pragma unroll
        for (int g0 = 0; g0 < 2; g0++)
            #pragma unroll
            for (int q = 0; q < 4; q++)
                N[g0*4+q] = M[q*4+0]*Cg[g0*4+0] + M[q*4+1]*Cg[g0*4+1]
                          + M[q*4+2]*Cg[g0*4+2] + M[q*4+3]*Cg[g0*4+3];
        #pragma unroll
        for (int k = 0; k < 8; k++) Cg[k] = N[k];
    }
    {   // axis q2 (PT[2]) : lane bits 3-4 -> shfl_xor 8,16,24
        const float* M = PT[2];
        float n[8];
        #pragma unroll
        for (int k = 0; k < 8; k++) {
            float s1 = __shfl_xor_sync(0xffffffffu, Cg[k], 8);
            float s2 = __shfl_xor_sync(0xffffffffu, Cg[k], 16);
            float s3 = __shfl_xor_sync(0xffffffffu, Cg[k], 24);
            n[k] = M[q2*4+q2]*Cg[k] + M[q2*4+(q2^1)]*s1
                 + M[q2*4+(q2^2)]*s2 + M[q2*4+(q2^3)]*s3;
        }
        #pragma unroll
        for (int k = 0; k < 8; k++) Cg[k] = n[k];
    }
    {   // axis q3 (PT[3]) : lane bits 1-2 -> shfl_xor 2,4,6
        const float* M = PT[3];
        float n[8];
        #pragma unroll
        for (int k = 0; k < 8; k++) {
            float s1 = __shfl_xor_sync(0xffffffffu, Cg[k], 2);
            float s2 = __shfl_xor_sync(0xffffffffu, Cg[k], 4);
            float s3 = __shfl_xor_sync(0xffffffffu, Cg[k], 6);
            n[k] = M[q3*4+q3]*Cg[k] + M[q3*4+(q3^1)]*s1
                 + M[q3*4+(q3^2)]*s2 + M[q3*4+(q3^3)]*s3;
        }
        #pragma unroll
        for (int k = 0; k < 8; k++) Cg[k] = n[k];
    }

    // ---- edge expansion (PTM cols I,Z) + D0 CZ scatter; warps split the work:
    //      warp -> p0 = wrp>>1, p4 pair = wrp&1; lane parity -> p4 low bit.
    {
        const int p0 = wrp >> 1;
        const float c00 = PT[0][p0*4], c0z = PT[0][p0*4+3];
        const int p4 = ((wrp & 1) << 1) | b4;
        const float* M4 = PT[4];
        #pragma unroll
        for (int r = 0; r < 4; r++) {
            float h  = c00 * Cg[r] + c0z * Cg[r + 4];       // own b4
            float ho = __shfl_xor_sync(0xffffffffu, h, 1);  // partner b4
            float h0 = b4 ? ho : h;
            float h1 = b4 ? h  : ho;
            float sg = M4[p4*4+0]*h0 + M4[p4*4+3]*h1;
            int p[5] = { p0, r, q2, q3, p4 };
            #pragma unroll
            for (int a = 0; a < 4; a++) {
                int wl = i - 2 + a;
                if (wl >= 0 && wl + 1 < NQ) {
                    int pa = p[a], pb = p[a+1];
                    bool xl = (pa==1)||(pa==2), xr = (pb==1)||(pb==2);
                    if (xl && xr && pa != pb) sg = -sg;
                    if (xr) p[a]   = pa ^ 3;
                    if (xl) p[a+1] = pb ^ 3;
                }
            }
            tF[p[0]*APAD + (p[1]<<6) + (p[2]<<4) + (p[3]<<2) + p[4]] = sg;
        }
    }
    __syncthreads();                      // B2

    // ---- per-sample contraction: 4 threads/sample (p0 slice = as) ----
    float dL = (i - 3 >= 0) ? m[0][2] : 1.f;
    float dR = (i + 3 < NQ) ? m[6][2] : 1.f;
    float v0c[4], v1c[4], v2c[4], v3c[4], v4c[4];
    v0c[0]=1.f; v0c[1]=dL*m[1][0]; v0c[2]=dL*m[1][1]; v0c[3]=m[1][2];
    v1c[0]=1.f; v1c[1]=m[2][0];    v1c[2]=m[2][1];    v1c[3]=m[2][2];
    v2c[0]=1.f; v2c[1]=m[3][0];    v2c[2]=m[3][1];    v2c[3]=m[3][2];
    v3c[0]=1.f; v3c[1]=m[4][0];    v3c[2]=m[4][1];    v3c[3]=m[4][2];
    v4c[0]=1.f; v4c[1]=dR*m[5][0]; v4c[2]=dR*m[5][1]; v4c[3]=m[5][2];

    const float4* Ta = reinterpret_cast<const float4*>(tF + as * APAD);
    float sb[4];
    #pragma unroll
    for (int q = 0; q < 4; q++) {
        float acc = 0.f;
        #pragma unroll
        for (int c = 0; c < 4; c++) {
            float sc = 0.f;
            #pragma unroll
            for (int d = 0; d < 4; d++) {
                float4 t4 = Ta[q*16 + c*4 + d];
                sc += v3c[d] * (t4.x*v4c[0] + t4.y*v4c[1] + t4.z*v4c[2] + t4.w*v4c[3]);
            }
            acc += v2c[c] * sc;
        }
        sb[q] = acc;
    }
    float z = v0c[as] * (v1c[0]*sb[0] + v1c[1]*sb[1] + v1c[2]*sb[2] + v1c[3]*sb[3]);
    z += __shfl_xor_sync(0xffffffffu, z, 1);
    z += __shfl_xor_sync(0xffffffffu, z, 2);
    if (as == 0) g_z[b * NQ + i] = z;

    // ---- fused FC head: last CTA of this chunk does the 64x6 GEMV ----
    __syncthreads();                      // B3
    if (tid == 0) {
        __threadfence();
        int old = atomicAdd(&g_cnt[chunk], 1);
        int e = (old == NQ - 1);
        if (e) {
            __threadfence();
            atomicExch(&g_cnt[chunk], 0);   // reset for next graph replay
        }
        s_elect = e;
    }
    __syncthreads();                      // B4
    if (s_elect) {
        for (int j = tid; j < SPC * NQ; j += 256)
            tF[j] = __ldcg(&g_z[chunk * SPC * NQ + j]);
        __syncthreads();
        for (int item = tid; item < SPC * NA; item += 256) {
            int s = item / NA, a = item % NA;
            float acc = fcb[a];
            #pragma unroll
            for (int k = 0; k < NQ; k++) acc += tF[s*NQ + k] * fcw[a*NQ + k];
            out[(chunk * SPC + s) * NA + a] = acc;
        }
    }
}

extern "C" void kernel_launch(void* const* d_in, const int* in_sizes, int n_in,
                              void* d_out, int out_size) {
    const float* x   = (const float*)d_in[0];   // [512,16]
    const float* W   = (const float*)d_in[1];   // [4,16,3]
    const float* fcw = (const float*)d_in[2];   // [6,16]
    const float* fcb = (const float*)d_in[3];   // [6]
    float* out = (float*)d_out;                 // [512,6]
    (void)in_sizes; (void)n_in; (void)out_size;
    dim3 grid(NQ, NCHUNK);
    vqc_fused<<<grid, 256>>>(x, W, fcw, fcb, out);
}

// round 10
// speedup vs baseline: 2.5582x; 1.0239x over previous
#include <cuda_runtime.h>
#include <math.h>

// PennyLaneBasicDQN: 16-qubit VQC (RY embed + 4x[Rot,CZ chain]) + linear head.
// Heisenberg light-cone + Pauli-transfer-matrix method (verified R3..R9).
// R10: build de-duplication — only warp 0 runs the register build (D1 gather +
// layer-1 axes), publishing the compact 256-tensor via smem; all warps do the
// expansion+D0 scatter from smem. Elect FC tail staged with float4 ldcg.

#define NQ 16
#define NA 6
#define BATCHSZ 512
#define NCHUNK 8
#define SPC 64
#define APAD 264          // padded p0-slice stride (floats)

__device__ __align__(16) float g_z[BATCHSZ * NQ];
__device__ int   g_cnt[NCHUNK] = {0};

struct C2 { float x, y; };
__device__ __forceinline__ C2 cmk(float a, float b){ C2 r; r.x=a; r.y=b; return r; }
__device__ __forceinline__ C2 cml(C2 a, C2 b){ return cmk(a.x*b.x - a.y*b.y, a.x*b.y + a.y*b.x); }
__device__ __forceinline__ C2 cad(C2 a, C2 b){ return cmk(a.x+b.x, a.y+b.y); }

// Column p of the 4x4 real PTM of conjugation O -> U^dag O U
__device__ __forceinline__ void ptm_col(const C2 u[4], int p, float col[4]) {
    C2 ud00 = cmk(u[0].x, -u[0].y), ud01 = cmk(u[2].x, -u[2].y);
    C2 ud10 = cmk(u[1].x, -u[1].y), ud11 = cmk(u[3].x, -u[3].y);
    C2 s00, s01, s10, s11;                 // sigma_p * U
    if (p == 0)      { s00=u[0]; s01=u[1]; s10=u[2]; s11=u[3]; }
    else if (p == 1) { s00=u[2]; s01=u[3]; s10=u[0]; s11=u[1]; }
    else if (p == 2) {
        s00 = cmk( u[2].y, -u[2].x);
        s01 = cmk( u[3].y, -u[3].x);
        s10 = cmk(-u[0].y,  u[0].x);
        s11 = cmk(-u[1].y,  u[1].x);
    } else           { s00=u[0]; s01=u[1]; s10=cmk(-u[2].x,-u[2].y); s11=cmk(-u[3].x,-u[3].y); }
    C2 A00 = cad(cml(ud00, s00), cml(ud01, s10));
    C2 A01 = cad(cml(ud00, s01), cml(ud01, s11));
    C2 A10 = cad(cml(ud10, s00), cml(ud11, s10));
    C2 A11 = cad(cml(ud10, s01), cml(ud11, s11));
    col[0] = 0.5f*(A00.x + A11.x);
    col[1] = 0.5f*(A01.x + A10.x);
    col[2] = 0.5f*(A10.y - A01.y);
    col[3] = 0.5f*(A00.x - A11.x);
}

// PennyLane Rot(phi,theta,omega) = RZ(omega) RY(theta) RZ(phi)
__device__ __forceinline__ void rot_u(const float* wp, C2 u[4]) {
    float phi = wp[0], th = wp[1], om = wp[2];
    float c, s; __sincosf(0.5f*th, &s, &c);
    float epx, epy, emx, emy;
    __sincosf(-0.5f*(phi+om), &epy, &epx);
    __sincosf(-0.5f*(phi-om), &emy, &emx);
    u[0] = cmk( epx*c,  epy*c);
    u[1] = cmk(-emx*s,  emy*s);
    u[2] = cmk( emx*s,  emy*s);
    u[3] = cmk( epx*c, -epy*c);
}

__global__ __launch_bounds__(256)
void vqc_fused(const float* __restrict__ x, const float* __restrict__ W,
               const float* __restrict__ fcw, const float* __restrict__ fcb,
               float* __restrict__ out)
{
    __shared__ float PT[15][16];          // conj-PTMs: layers 1..3 x window pos 0..4
    __shared__ float bx[7][3], bz[7][3];  // layer-0 Bloch columns, wires i-3..i+3
    __shared__ float sC[256];             // compact tensor [b0*4+q1][lane=(q2,q3,b4)]
    __shared__ __align__(16) float tF[4 * APAD];
    __shared__ int s_elect;

    const int i     = blockIdx.x;         // measured qubit
    const int chunk = blockIdx.y;         // 64-sample chunk
    const int tid   = threadIdx.x;
    const int lane  = tid & 31;
    const int wrp   = tid >> 5;
    const int sl    = tid >> 2;           // local sample 0..63
    const int as    = tid & 3;            // p0 slice in contraction
    const int b     = chunk * SPC + sl;

    // issue x loads early (hidden behind prologue)
    float xv[7];
    #pragma unroll
    for (int k = 0; k < 7; k++) {
        int w = i - 3 + k;
        xv[k] = (w >= 0 && w < NQ) ? x[b*NQ + w] : 0.f;
    }

    // ---- prologue: column-parallel PTM + Bloch construction ----
    if (tid < 60) {
        int id = tid >> 2, p = tid & 3;
        int l = 1 + id / 5, a = id % 5;
        int w = i - 2 + a;
        float col[4];
        if (w >= 0 && w < NQ) {
            C2 u[4]; rot_u(W + (l*NQ + w)*3, u);
            ptm_col(u, p, col);
        } else {
            #pragma unroll
            for (int q = 0; q < 4; q++) col[q] = (q == p) ? 1.f : 0.f;
        }
        #pragma unroll
        for (int q = 0; q < 4; q++) PT[id][q*4 + p] = col[q];
    } else if (tid >= 64 && tid < 78) {
        int id = tid - 64;
        int k = id >> 1;
        int p = (id & 1) ? 3 : 1;
        int w = i - 3 + k;
        float col[4] = {0.f, 0.f, 0.f, 0.f};
        if (w >= 0 && w < NQ) {
            C2 u[4]; rot_u(W + w*3, u);
            C2 v[4] = { cmk(u[0].x,-u[0].y), cmk(u[2].x,-u[2].y),
                        cmk(u[1].x,-u[1].y), cmk(u[3].x,-u[3].y) };
            ptm_col(v, p, col);
        }
        float* dstv = (p == 1) ? bx[k] : bz[k];
        dstv[0] = col[1]; dstv[1] = col[2]; dstv[2] = col[3];
    }
    __syncthreads();                      // B1

    const int q2 = (lane >> 3) & 3, q3 = (lane >> 1) & 3, b4 = lane & 1;

    // ---- warp 0 ONLY: register build (verified R9) -> compact sC ----
    if (wrp == 0) {
        const int ex1 = (i >= 1), ex2 = (i <= 14);
        const int fX = (ex1 ? 48 : 0) + 4 + (ex2 ? 3 : 0);
        const int fY = fX + 4;
        const float cI = PT[12][3], cX = PT[12][7], cY = PT[12][11], cZ = PT[12][15];
        float v0, v1;   // lane holds f=lane (v0), f=32+lane (v1); f = p1*16+p2*4+p3
        {
            int f0 = lane, f1 = 32 + lane;
            v0 = (f0==0)?cI : (f0==12)?cZ : (f0==fX)?cX : (f0==fY)?cY : 0.f;
            v1 = (f1==0)?cI : (f1==12)?cZ : (f1==fX)?cX : (f1==fY)?cY : 0.f;
        }
        {   // layer-2 axis p1 (PT[6])
            const float* M = PT[6];
            float o0 = __shfl_xor_sync(0xffffffffu, v0, 16);
            float o1 = __shfl_xor_sync(0xffffffffu, v1, 16);
            int q0 = (lane >> 4) & 1;
            int r0 = q0, r1 = q0 ^ 2;
            float n0 = M[r0*4+q0]*v0 + M[r0*4+(q0^1)]*o0 + M[r0*4+(q0^2)]*v1 + M[r0*4+(q0^3)]*o1;
            float n1 = M[r1*4+q0]*v0 + M[r1*4+(q0^1)]*o0 + M[r1*4+(q0^2)]*v1 + M[r1*4+(q0^3)]*o1;
            v0 = n0; v1 = n1;
        }
        {   // layer-2 axis p2 (PT[7])
            const float* M = PT[7];
            int po = (lane >> 2) & 3;
            float a1 = __shfl_xor_sync(0xffffffffu, v0, 4);
            float a2 = __shfl_xor_sync(0xffffffffu, v0, 8);
            float a3 = __shfl_xor_sync(0xffffffffu, v0, 12);
            float b1 = __shfl_xor_sync(0xffffffffu, v1, 4);
            float b2 = __shfl_xor_sync(0xffffffffu, v1, 8);
            float b3 = __shfl_xor_sync(0xffffffffu, v1, 12);
            v0 = M[po*4+po]*v0 + M[po*4+(po^1)]*a1 + M[po*4+(po^2)]*a2 + M[po*4+(po^3)]*a3;
            v1 = M[po*4+po]*v1 + M[po*4+(po^1)]*b1 + M[po*4+(po^2)]*b2 + M[po*4+(po^3)]*b3;
        }
        {   // layer-2 axis p3 (PT[8])
            const float* M = PT[8];
            int po = lane & 3;
            float a1 = __shfl_xor_sync(0xffffffffu, v0, 1);
            float a2 = __shfl_xor_sync(0xffffffffu, v0, 2);
            float a3 = __shfl_xor_sync(0xffffffffu, v0, 3);
            float b1 = __shfl_xor_sync(0xffffffffu, v1, 1);
            float b2 = __shfl_xor_sync(0xffffffffu, v1, 2);
            float b3 = __shfl_xor_sync(0xffffffffu, v1, 3);
            v0 = M[po*4+po]*v0 + M[po*4+(po^1)]*a1 + M[po*4+(po^2)]*a2 + M[po*4+(po^3)]*a3;
            v1 = M[po*4+po]*v1 + M[po*4+(po^1)]*b1 + M[po*4+(po^2)]*b2 + M[po*4+(po^3)]*b3;
        }

        // D1 as a register GATHER (CZ label map is an involution)
        const int exA0 = (i >= 2), exA1 = (i >= 1), exA2 = (i <= 14), exA3 = (i <= 13);
        float Cg[8];
        {
            const bool need4 = (exA3 && ((q3 == 1) || (q3 == 2)));
            const bool ok4 = (b4 == (need4 ? 1 : 0));
            #pragma unroll
            for (int j = 0; j < 4; j++) {
                int p1 = j, p2 = q2, p3 = q3; float s = 1.f;
                if (exA1) {
                    bool xl = (p1==1)||(p1==2), xr = (p2==1)||(p2==2);
                    if (xl && xr && p1 != p2) s = -s;
                    int np1 = xr ? p1^3 : p1, np2 = xl ? p2^3 : p2;
                    p1 = np1; p2 = np2;
                }
                if (exA2) {
                    bool xl = (p2==1)||(p2==2), xr = (p3==1)||(p3==2);
                    if (xl && xr && p2 != p3) s = -s;
                    int np2 = xr ? p2^3 : p2, np3 = xl ? p3^3 : p3;
                    p2 = np2; p3 = np3;
                }
                int fsrc = p1*16 + p2*4 + p3;
                float a0 = __shfl_sync(0xffffffffu, v0, fsrc & 31);
                float a1 = __shfl_sync(0xffffffffu, v1, fsrc & 31);
                float val = s * ((fsrc & 32) ? a1 : a0);
                bool need0 = (exA0 && ((p1 == 1) || (p1 == 2)));
                Cg[j]     = (ok4 && !need0) ? val : 0.f;
                Cg[j + 4] = (ok4 &&  need0) ? val : 0.f;
            }
        }
        {   // layer-1 axis q1 (PT[1]) : register 4x4 within each b0 group
            const float* M = PT[1];
            float N[8];
            #pragma unroll
            for (int g0 = 0; g0 < 2; g0++)
                #pragma unroll
                for (int q = 0; q < 4; q++)
                    N[g0*4+q] = M[q*4+0]*Cg[g0*4+0] + M[q*4+1]*Cg[g0*4+1]
                              + M[q*4+2]*Cg[g0*4+2] + M[q*4+3]*Cg[g0*4+3];
            #pragma unroll
            for (int k = 0; k < 8; k++) Cg[k] = N[k];
        }
        {   // layer-1 axis q2 (PT[2]) : shfl_xor 8,16,24
            const float* M = PT[2];
            float n[8];
            #pragma unroll
            for (int k = 0; k < 8; k++) {
                float s1 = __shfl_xor_sync(0xffffffffu, Cg[k], 8);
                float s2 = __shfl_xor_sync(0xffffffffu, Cg[k], 16);
                float s3 = __shfl_xor_sync(0xffffffffu, Cg[k], 24);
                n[k] = M[q2*4+q2]*Cg[k] + M[q2*4+(q2^1)]*s1
                     + M[q2*4+(q2^2)]*s2 + M[q2*4+(q2^3)]*s3;
            }
            #pragma unroll
            for (int k = 0; k < 8; k++) Cg[k] = n[k];
        }
        {   // layer-1 axis q3 (PT[3]) : shfl_xor 2,4,6
            const float* M = PT[3];
            float n[8];
            #pragma unroll
            for (int k = 0; k < 8; k++) {
                float s1 = __shfl_xor_sync(0xffffffffu, Cg[k], 2);
                float s2 = __shfl_xor_sync(0xffffffffu, Cg[k], 4);
                float s3 = __shfl_xor_sync(0xffffffffu, Cg[k], 6);
                n[k] = M[q3*4+q3]*Cg[k] + M[q3*4+(q3^1)]*s1
                     + M[q3*4+(q3^2)]*s2 + M[q3*4+(q3^3)]*s3;
            }
            #pragma unroll
            for (int k = 0; k < 8; k++) Cg[k] = n[k];
        }
        #pragma unroll
        for (int k = 0; k < 8; k++) sC[k*32 + lane] = Cg[k];
    }

    // per-sample Bloch vectors (warps 1-7 do this while warp 0 builds)
    float m[7][3];
    #pragma unroll
    for (int k = 0; k < 7; k++) {
        float sx, cx; __sincosf(xv[k], &sx, &cx);
        m[k][0] = sx*bx[k][0] + cx*bz[k][0];
        m[k][1] = sx*bx[k][1] + cx*bz[k][1];
        m[k][2] = sx*bx[k][2] + cx*bz[k][2];
    }
    __syncthreads();                      // B2: sC published

    // ---- edge expansion (PTM cols I,Z) + D0 CZ scatter; all 8 warps:
    //      warp -> p0 = wrp>>1, p4 pair = wrp&1; lane parity -> p4 low bit.
    {
        const int p0 = wrp >> 1;
        const float c00 = PT[0][p0*4], c0z = PT[0][p0*4+3];
        const int p4 = ((wrp & 1) << 1) | b4;
        const float* M4 = PT[4];
        const int le = lane & ~1, lo = lane | 1;
        #pragma unroll
        for (int r = 0; r < 4; r++) {
            float h0 = c00 * sC[r*32 + le] + c0z * sC[(4+r)*32 + le];  // b4=0
            float h1 = c00 * sC[r*32 + lo] + c0z * sC[(4+r)*32 + lo];  // b4=1
            float sg = M4[p4*4+0]*h0 + M4[p4*4+3]*h1;
            int p[5] = { p0, r, q2, q3, p4 };
            #pragma unroll
            for (int a = 0; a < 4; a++) {
                int wl = i - 2 + a;
                if (wl >= 0 && wl + 1 < NQ) {
                    int pa = p[a], pb = p[a+1];
                    bool xl = (pa==1)||(pa==2), xr = (pb==1)||(pb==2);
                    if (xl && xr && pa != pb) sg = -sg;
                    if (xr) p[a]   = pa ^ 3;
                    if (xl) p[a+1] = pb ^ 3;
                }
            }
            tF[p[0]*APAD + (p[1]<<6) + (p[2]<<4) + (p[3]<<2) + p[4]] = sg;
        }
    }
    __syncthreads();                      // B3

    // ---- per-sample contraction: 4 threads/sample (p0 slice = as) ----
    float dL = (i - 3 >= 0) ? m[0][2] : 1.f;
    float dR = (i + 3 < NQ) ? m[6][2] : 1.f;
    float v0c[4], v1c[4], v2c[4], v3c[4], v4c[4];
    v0c[0]=1.f; v0c[1]=dL*m[1][0]; v0c[2]=dL*m[1][1]; v0c[3]=m[1][2];
    v1c[0]=1.f; v1c[1]=m[2][0];    v1c[2]=m[2][1];    v1c[3]=m[2][2];
    v2c[0]=1.f; v2c[1]=m[3][0];    v2c[2]=m[3][1];    v2c[3]=m[3][2];
    v3c[0]=1.f; v3c[1]=m[4][0];    v3c[2]=m[4][1];    v3c[3]=m[4][2];
    v4c[0]=1.f; v4c[1]=dR*m[5][0]; v4c[2]=dR*m[5][1]; v4c[3]=m[5][2];

    const float4* Ta = reinterpret_cast<const float4*>(tF + as * APAD);
    float sb[4];
    #pragma unroll
    for (int q = 0; q < 4; q++) {
        float acc = 0.f;
        #pragma unroll
        for (int c = 0; c < 4; c++) {
            float sc = 0.f;
            #pragma unroll
            for (int d = 0; d < 4; d++) {
                float4 t4 = Ta[q*16 + c*4 + d];
                sc += v3c[d] * (t4.x*v4c[0] + t4.y*v4c[1] + t4.z*v4c[2] + t4.w*v4c[3]);
            }
            acc += v2c[c] * sc;
        }
        sb[q] = acc;
    }
    float z = v0c[as] * (v1c[0]*sb[0] + v1c[1]*sb[1] + v1c[2]*sb[2] + v1c[3]*sb[3]);
    z += __shfl_xor_sync(0xffffffffu, z, 1);
    z += __shfl_xor_sync(0xffffffffu, z, 2);
    if (as == 0) g_z[b * NQ + i] = z;

    // ---- fused FC head: last CTA of this chunk does the 64x6 GEMV ----
    __syncthreads();                      // B4
    if (tid == 0) {
        __threadfence();
        int old = atomicAdd(&g_cnt[chunk], 1);
        int e = (old == NQ - 1);
        if (e) {
            __threadfence();
            atomicExch(&g_cnt[chunk], 0);   // reset for next graph replay
        }
        s_elect = e;
    }
    __syncthreads();                      // B5
    if (s_elect) {
        // stage chunk's z-block (1024 floats) with one float4 ldcg per thread
        const float4* zsrc = reinterpret_cast<const float4*>(g_z + chunk * SPC * NQ);
        reinterpret_cast<float4*>(tF)[tid] = __ldcg(&zsrc[tid]);
        __syncthreads();
        for (int item = tid; item < SPC * NA; item += 256) {
            int s = item / NA, a = item % NA;
            float acc = fcb[a];
            #pragma unroll
            for (int k = 0; k < NQ; k++) acc += tF[s*NQ + k] * fcw[a*NQ + k];
            out[(chunk * SPC + s) * NA + a] = acc;
        }
    }
}

extern "C" void kernel_launch(void* const* d_in, const int* in_sizes, int n_in,
                              void* d_out, int out_size) {
    const float* x   = (const float*)d_in[0];   // [512,16]
    const float* W   = (const float*)d_in[1];   // [4,16,3]
    const float* fcw = (const float*)d_in[2];   // [6,16]
    const float* fcb = (const float*)d_in[3];   // [6]
    float* out = (float*)d_out;                 // [512,6]
    (void)in_sizes; (void)n_in; (void)out_size;
    dim3 grid(NQ, NCHUNK);
    vqc_fused<<<grid, 256>>>(x, W, fcw, fcb, out);
}